// round 8
// baseline (speedup 1.0000x reference)
#include <cuda_runtime.h>
#include <cstdint>

#define NB    32
#define NT    24
#define SZ    768
#define NPAIR 3              // column pairs (256 cols each) -> producer units
#define NTHR  1024
#define NWARP 32             // warps per block; 16 per half
#define RPF4  (SZ / 4)       // 192 float4 per matrix row
#define RPW   48             // rows per warp (768 / 16 warps-per-half)
#define PRE   8              // rows register-prefetched across the sync

// post-ReLU carry produced at step t, consumed at step t+1
__device__ float g_carry[NT][NB][SZ];
// per-pair flags: g_flag[t][b][p] = 1 when cols [256p,256p+256) of carry(t,b) visible
__device__ int g_flag[NT][NB][NPAIR];

__global__ void init_flags_kernel() {
    int i = blockIdx.x * blockDim.x + threadIdx.x;
    if (i < NT * NB * NPAIR) ((int*)g_flag)[i] = 0;
}

__global__ void __launch_bounds__(NTHR, 1)   // caps regs at 64
scan_kernel(const float* __restrict__ inp,
            const float* __restrict__ param,
            float* __restrict__ out)
{
    __shared__ float  s_y[SZ];               // 3 KB carry vector (shared by both halves)
    __shared__ float4 s_red[2][16][32];      // 16 KB partials, per half

    const int p    = blockIdx.x;             // pair 0..2 (columns 256p .. 256p+255)
    const int b    = blockIdx.y;             // batch
    const int tid  = threadIdx.x;
    const int w    = tid >> 5;
    const int lane = tid & 31;
    const int half = w >> 4;                 // 0: cols [0,128), 1: cols [128,256) of pair
    const int wl   = w & 15;                 // warp id within half
    const int kbase = p * 256 + half * 128;

    // float4 view of this batch's matrices, offset to this half's column slab.
    const float4* matb = (const float4*)(inp + (size_t)b * NT * SZ * SZ + kbase);

    for (int t = 0; t < NT; ++t) {
        const float4* pm = matb + (size_t)t * SZ * RPF4;

        // ---- PREFETCH ACROSS THE SYNC: rows j=0..7 for this warp ----
        // Addresses don't depend on the carry; fills the wait bubble with traffic.
        float4 m[PRE];
        #pragma unroll
        for (int u = 0; u < PRE; ++u)
            m[u] = __ldcs(&pm[(size_t)(wl + 16 * u) * RPF4 + lane]);

        // ---- wait for batch b's previous step (3 pair flags), stage carry ----
        if (t > 0) {
            if (tid == 0) {
                #pragma unroll
                for (int q = 0; q < NPAIR; ++q) {
                    volatile int* f = &g_flag[t - 1][b][q];
                    while (*f == 0) __nanosleep(32);
                }
                __threadfence();             // acquire
            }
            __syncthreads();
            if (tid < SZ)
                s_y[tid] = __ldcg(&g_carry[t - 1][b][tid]);
        } else {
            if (tid < SZ)
                s_y[tid] = param[tid] + 1.0f;
        }
        __syncthreads();

        // ---- compute: prefetched rows, then fully-unrolled stream ----
        float4 acc = make_float4(0.f, 0.f, 0.f, 0.f);
        #pragma unroll
        for (int u = 0; u < PRE; ++u) {
            float yv = s_y[wl + 16 * u];
            acc.x = fmaf(yv, m[u].x, acc.x);
            acc.y = fmaf(yv, m[u].y, acc.y);
            acc.z = fmaf(yv, m[u].z, acc.z);
            acc.w = fmaf(yv, m[u].w, acc.w);
        }
        #pragma unroll
        for (int j = PRE; j < RPW; ++j) {    // ptxas front-batches these LDG.128s
            float4 mm = __ldcs(&pm[(size_t)(wl + 16 * j) * RPF4 + lane]);
            float yv  = s_y[wl + 16 * j];
            acc.x = fmaf(yv, mm.x, acc.x);
            acc.y = fmaf(yv, mm.y, acc.y);
            acc.z = fmaf(yv, mm.z, acc.z);
            acc.w = fmaf(yv, mm.w, acc.w);
        }

        // ---- cross-warp reduction, per half ----
        s_red[half][wl][lane] = acc;
        __syncthreads();

        if (tid < 256) {
            const int ho = tid >> 7;         // which half's columns
            const int r  = tid & 127;        // column within the half's slab
            float sum = 0.f;
            #pragma unroll
            for (int ww = 0; ww < 16; ++ww)
                sum += ((const float*)&s_red[ho][ww][r >> 2])[r & 3];
            const int k = p * 256 + ho * 128 + r;
            if (t == NT - 1) {
                out[b * SZ + k] = sum;                     // pre-ReLU final step
            } else {
                __stcg(&g_carry[t][b][k], fmaxf(sum, 0.f));
            }
            __threadfence();                               // release (writers only)
        }
        __syncthreads();                                   // writers fenced before flag
        if (t < NT - 1 && tid == 0) {
            atomicExch(&g_flag[t][b][p], 1);
        }
    }
}

extern "C" void kernel_launch(void* const* d_in, const int* in_sizes, int n_in,
                              void* d_out, int out_size)
{
    const float* inp   = (const float*)d_in[0];   // [32,24,768,768] f32
    const float* param = (const float*)d_in[1];   // [768] f32
    float* out         = (float*)d_out;           // [32,768] f32

    init_flags_kernel<<<5, 512>>>();
    dim3 grid(NPAIR, NB);
    scan_kernel<<<grid, NTHR>>>(inp, param, out);
}

// round 11
// speedup vs baseline: 1.0186x; 1.0186x over previous
#include <cuda_runtime.h>
#include <cstdint>

#define NB    32
#define NT    24
#define SZ    768
#define NS    6
#define SLAB  128
#define NTHR  512
#define NWARP 16
#define RPF4  (SZ / 4)       // 192 float4 per matrix row
#define RPW   48             // rows per warp
#define PRE   8              // rows register-prefetched across the wait

// post-ReLU carry produced at step t, consumed at step t+1
__device__ float g_carry[NT][NB][SZ];
// y0 = param + 1 (precomputed so all steps read carries via one uniform path)
__device__ float g_y0[SZ];
// per-slab flags: g_flag[t][b][s] = 1 when slab s of carry(t,b) is visible
__device__ int g_flag[NT][NB][NS];

__global__ void init_kernel(const float* __restrict__ param) {
    int i = threadIdx.x;                  // 768 threads
    if (i < NT * NB * NS) ((int*)g_flag)[i] = 0;
    g_y0[i] = param[i] + 1.0f;
}

__global__ void __launch_bounds__(NTHR, 2)   // cap regs at 64: 2 blocks/SM co-residency
scan_kernel(const float* __restrict__ inp,
            const float* __restrict__ param,
            float* __restrict__ out)
{
    __shared__ float4 s_red[NWARP][32];       // 8 KB partials

    const int s    = blockIdx.x;              // slab 0..5
    const int b    = blockIdx.y;              // batch
    const int tid  = threadIdx.x;
    const int w    = tid >> 5;
    const int lane = tid & 31;
    const int kbase = s * SLAB;

    // float4 view of this batch's matrices, offset to our column slab.
    const float4* matb = (const float4*)(inp + (size_t)b * NT * SZ * SZ + kbase);

    // Prologue: register-prefetch rows j=0..7 of step 0.
    const float4* pm = matb;
    float4 m[PRE];
    #pragma unroll
    for (int u = 0; u < PRE; ++u)
        m[u] = __ldcs(&pm[(size_t)(w + NWARP * u) * RPF4 + lane]);

    for (int t = 0; t < NT; ++t) {
        // ---- per-warp wait: lanes 0..5 watch the 6 producer flags ----
        if (t > 0) {
            const volatile int* f = (const volatile int*)g_flag[t - 1][b];
            for (;;) {
                int fv = (lane < NS) ? f[lane] : 1;
                if (__all_sync(0xffffffffu, fv != 0)) break;
                __nanosleep(32);
            }
            __threadfence();                  // acquire
        }

        // carry source for this step (uniform path; t=0 reads precomputed y0)
        const float* ysrc = (t == 0) ? g_y0 : g_carry[t - 1][b];

        // ---- compute: prefetched rows first, then fully-unrolled stream ----
        // carry values are lane-uniform __ldcg broadcasts (1 wavefront each)
        float4 acc = make_float4(0.f, 0.f, 0.f, 0.f);
        #pragma unroll
        for (int u = 0; u < PRE; ++u) {
            float yv = __ldcg(&ysrc[w + NWARP * u]);
            acc.x = fmaf(yv, m[u].x, acc.x);
            acc.y = fmaf(yv, m[u].y, acc.y);
            acc.z = fmaf(yv, m[u].z, acc.z);
            acc.w = fmaf(yv, m[u].w, acc.w);
        }
        #pragma unroll
        for (int j = PRE; j < RPW; ++j) {     // ptxas front-batches these LDG.128s
            float4 mm = __ldcs(&pm[(size_t)(w + NWARP * j) * RPF4 + lane]);
            float yv  = __ldcg(&ysrc[w + NWARP * j]);
            acc.x = fmaf(yv, mm.x, acc.x);
            acc.y = fmaf(yv, mm.y, acc.y);
            acc.z = fmaf(yv, mm.z, acc.z);
            acc.w = fmaf(yv, mm.w, acc.w);
        }

        // ---- publish partials, then prefetch t+1 BEFORE the barrier ----
        s_red[w][lane] = acc;
        if (t < NT - 1) {
            pm += (size_t)SZ * RPF4;
            #pragma unroll
            for (int u = 0; u < PRE; ++u)
                m[u] = __ldcs(&pm[(size_t)(w + NWARP * u) * RPF4 + lane]);
        }
        __syncthreads();

        // ---- final reduction over 16 warps, write carry / output ----
        if (tid < SLAB) {
            float sum = 0.f;
            #pragma unroll
            for (int ww = 0; ww < NWARP; ++ww)
                sum += ((const float*)&s_red[ww][tid >> 2])[tid & 3];
            const int k = kbase + tid;
            if (t == NT - 1) {
                out[b * SZ + k] = sum;                    // pre-ReLU final step
            } else {
                __stcg(&g_carry[t][b][k], fmaxf(sum, 0.f));
            }
            __threadfence();                              // release (writers only)
        }
        __syncthreads();                                  // writers fenced before flag
        if (t < NT - 1 && tid == 0) {
            atomicExch(&g_flag[t][b][s], 1);
        }
    }
}

extern "C" void kernel_launch(void* const* d_in, const int* in_sizes, int n_in,
                              void* d_out, int out_size)
{
    const float* inp   = (const float*)d_in[0];   // [32,24,768,768] f32
    const float* param = (const float*)d_in[1];   // [768] f32
    float* out         = (float*)d_out;           // [32,768] f32

    init_kernel<<<1, SZ>>>(param);
    dim3 grid(NS, NB);
    scan_kernel<<<grid, NTHR>>>(inp, param, out);
}

// round 12
// speedup vs baseline: 1.1023x; 1.0822x over previous
#include <cuda_runtime.h>
#include <cstdint>

#define NB    32
#define NT    24
#define SZ    768
#define NS    12             // 12 slabs of 64 columns -> 384 blocks (>=2/SM everywhere)
#define SLAB  64
#define NTHR  256
#define NWARP 8
#define RPF4  (SZ / 4)       // 192 float4 per matrix row
#define ITERS 48             // row-pairs per warp (768 rows / (8 warps * 2 rows))
#define PRE   8              // iterations register-prefetched across the wait

// post-ReLU carry produced at step t, consumed at step t+1
__device__ float g_carry[NT][NB][SZ];
// per-slab flags: g_flag[t][b][s] = 1 when slab s of carry(t,b) is visible
__device__ int g_flag[NT][NB][NS];

__global__ void init_flags_kernel() {
    int i = blockIdx.x * blockDim.x + threadIdx.x;
    if (i < NT * NB * NS) ((int*)g_flag)[i] = 0;
}

#define FMA4(yv, mm)                          \
    acc.x = fmaf((yv), (mm).x, acc.x);        \
    acc.y = fmaf((yv), (mm).y, acc.y);        \
    acc.z = fmaf((yv), (mm).z, acc.z);        \
    acc.w = fmaf((yv), (mm).w, acc.w);

__global__ void __launch_bounds__(NTHR, 4)   // caps regs at 64; 4 blocks/SM capacity
scan_kernel(const float* __restrict__ inp,
            const float* __restrict__ param,
            float* __restrict__ out)
{
    __shared__ float  s_y[SZ];                // 3 KB staged carry
    __shared__ float4 s_red[NWARP][2][16];    // 4 KB partials (warp x row-parity x col4)

    const int s    = blockIdx.x;              // slab 0..11, columns [64s, 64s+64)
    const int b    = blockIdx.y;              // batch
    const int tid  = threadIdx.x;
    const int w    = tid >> 5;
    const int lane = tid & 31;
    const int half = lane >> 4;               // which row of the pair
    const int cl   = lane & 15;               // float4 column within slab
    const int kbase = s * SLAB;

    // float4 view of this batch's matrices, offset to our 64-col slab.
    // Two rows per warp-load: lanes 0-15 -> row r (256B), lanes 16-31 -> row r+1.
    const float4* matb = (const float4*)(inp + (size_t)b * NT * SZ * SZ + kbase);
    const float4* pm = matb;

    // Prologue: prefetch first PRE iterations of step 0.
    float4 m[PRE];
    #pragma unroll
    for (int u = 0; u < PRE; ++u) {
        const int row = 2 * (w + NWARP * u) + half;
        m[u] = __ldcs(&pm[(size_t)row * RPF4 + cl]);
    }

    for (int t = 0; t < NT; ++t) {
        // ---- wait for batch b's previous step: warp 0 lanes 0..11 poll in parallel ----
        if (t > 0) {
            if (w == 0) {
                const volatile int* f = (const volatile int*)g_flag[t - 1][b];
                for (;;) {
                    int fv = (lane < NS) ? f[lane] : 1;
                    if (__all_sync(0xffffffffu, fv != 0)) break;
                    __nanosleep(32);
                }
                __threadfence();              // acquire
            }
            __syncthreads();
            for (int i = tid; i < SZ; i += NTHR)
                s_y[i] = __ldcg(&g_carry[t - 1][b][i]);
        } else {
            for (int i = tid; i < SZ; i += NTHR)
                s_y[i] = param[i] + 1.0f;
        }
        __syncthreads();

        // ---- compute: prefetched rows, then pure stream (1 LDG + 1 LDS + 4 FMA) ----
        float4 acc = make_float4(0.f, 0.f, 0.f, 0.f);
        #pragma unroll
        for (int u = 0; u < PRE; ++u) {
            const float yv = s_y[2 * (w + NWARP * u) + half];
            FMA4(yv, m[u]);
        }
        #pragma unroll
        for (int j = PRE; j < ITERS; ++j) {   // fully unrolled: ptxas front-batches
            const int row = 2 * (w + NWARP * j) + half;
            const float4 mm = __ldcs(&pm[(size_t)row * RPF4 + cl]);
            const float  yv = s_y[row];
            FMA4(yv, mm);
        }

        // ---- publish partials, then prefetch t+1 BEFORE the barriers ----
        s_red[w][half][cl] = acc;
        if (t < NT - 1) {
            pm += (size_t)SZ * RPF4;
            #pragma unroll
            for (int u = 0; u < PRE; ++u) {
                const int row = 2 * (w + NWARP * u) + half;
                m[u] = __ldcs(&pm[(size_t)row * RPF4 + cl]);
            }
        }
        __syncthreads();

        // ---- reduce 16 partials per column, write carry / output ----
        if (tid < SLAB) {
            float sum = 0.f;
            #pragma unroll
            for (int ww = 0; ww < NWARP; ++ww) {
                sum += ((const float*)&s_red[ww][0][tid >> 2])[tid & 3];
                sum += ((const float*)&s_red[ww][1][tid >> 2])[tid & 3];
            }
            const int k = kbase + tid;
            if (t == NT - 1) {
                out[b * SZ + k] = sum;                    // pre-ReLU final step
            } else {
                __stcg(&g_carry[t][b][k], fmaxf(sum, 0.f));
            }
            __threadfence();                              // release (writers only)
        }
        __syncthreads();                                  // writers fenced before flag
        if (t < NT - 1 && tid == 0) {
            atomicExch(&g_flag[t][b][s], 1);
        }
    }
}

extern "C" void kernel_launch(void* const* d_in, const int* in_sizes, int n_in,
                              void* d_out, int out_size)
{
    const float* inp   = (const float*)d_in[0];   // [32,24,768,768] f32
    const float* param = (const float*)d_in[1];   // [768] f32
    float* out         = (float*)d_out;           // [32,768] f32

    init_flags_kernel<<<18, 512>>>();
    dim3 grid(NS, NB);
    scan_kernel<<<grid, NTHR>>>(inp, param, out);
}

// round 14
// speedup vs baseline: 1.1052x; 1.0026x over previous
#include <cuda_runtime.h>
#include <cstdint>

#define NB    32
#define NT    24
#define SZ    768
#define NS    6
#define SLAB  128
#define NTHR  512
#define NWARP 16
#define RPF4  (SZ / 4)       // 192 float4 per matrix row
#define RPW   48             // rows per warp
#define PRE   8              // register-prefetch rows per warp: j = 0..7
#define SMJ0  8              // smem-prefetch rows per warp: j = 8..11
#define SMJ1  12
#define SMROWS ((SMJ1 - SMJ0) * NWARP)   // 64 global rows (128..191)
#define SMCHUNKS (SMROWS * 32)           // 2048 x 16B = 32KB
#define CPT   (SMCHUNKS / NTHR)          // 4 cp.async per thread

// post-ReLU carry produced at step t, consumed at step t+1
__device__ float g_carry[NT][NB][SZ];
// per-slab flags: g_flag[t][b][s] = 1 when slab s of carry(t,b) is visible
__device__ int g_flag[NT][NB][NS];

__global__ void init_flags_kernel() {
    ((int*)g_flag)[threadIdx.x] = 0;      // 768 threads >= NT*NB*NS/... (24*32*6=4608)
}

__global__ void init_flags_kernel2() {
    int i = blockIdx.x * blockDim.x + threadIdx.x;
    if (i < NT * NB * NS) ((int*)g_flag)[i] = 0;
}

__device__ __forceinline__ void cp_async16(uint32_t saddr, const void* gaddr) {
    asm volatile("cp.async.cg.shared.global [%0], [%1], 16;\n"
                 :: "r"(saddr), "l"(gaddr));
}

#define FMA4(yv, mm)                          \
    acc.x = fmaf((yv), (mm).x, acc.x);        \
    acc.y = fmaf((yv), (mm).y, acc.y);        \
    acc.z = fmaf((yv), (mm).z, acc.z);        \
    acc.w = fmaf((yv), (mm).w, acc.w);

__global__ void __launch_bounds__(NTHR, 2)   // cap regs at 64: 2 blocks/SM co-residency
scan_kernel(const float* __restrict__ inp,
            const float* __restrict__ param,
            float* __restrict__ out)
{
    __shared__ float  s_y[SZ];                       // 3 KB staged carry
    __shared__ float  s_red[NWARP][SLAB];            // 8 KB partials
    __shared__ float4 s_mat[SMROWS * 32];            // 32 KB rows 128..191

    const int s    = blockIdx.x;              // slab 0..5
    const int b    = blockIdx.y;              // batch
    const int tid  = threadIdx.x;
    const int w    = tid >> 5;
    const int lane = tid & 31;
    const int kbase = s * SLAB;

    const uint32_t s_mat_base = (uint32_t)__cvta_generic_to_shared(s_mat);

    // float4 view of this batch's matrices, offset to our column slab.
    const float4* matb = (const float4*)(inp + (size_t)b * NT * SZ * SZ + kbase);
    const float4* pm = matb;

    // ---- prologue: prefetch step 0 (registers + cp.async tile) ----
    float4 m[PRE];
    #pragma unroll
    for (int u = 0; u < PRE; ++u)
        m[u] = __ldcs(&pm[(size_t)(w + NWARP * u) * RPF4 + lane]);
    #pragma unroll
    for (int k = 0; k < CPT; ++k) {
        int c   = tid + NTHR * k;                 // 0..2047
        int row = (SMJ0 * NWARP) + (c >> 5);
        int ln  = c & 31;
        cp_async16(s_mat_base + (uint32_t)c * 16,
                   &pm[(size_t)row * RPF4 + ln]);
    }
    asm volatile("cp.async.commit_group;\n" ::: "memory");

    for (int t = 0; t < NT; ++t) {
        // ---- per-warp wait + per-warp carry staging (overlapped across warps) ----
        if (t > 0) {
            const volatile int* f = (const volatile int*)g_flag[t - 1][b];
            for (;;) {
                int fv = (lane < NS) ? f[lane] : 1;
                if (__all_sync(0xffffffffu, fv != 0)) break;
                __nanosleep(32);
            }
            __threadfence();                      // acquire
            // warp w stages s_y[48w .. 48w+47]
            const int base = w * 48;
            s_y[base + lane] = __ldcg(&g_carry[t - 1][b][base + lane]);
            if (lane < 16)
                s_y[base + 32 + lane] = __ldcg(&g_carry[t - 1][b][base + 32 + lane]);
        } else {
            const int base = w * 48;
            s_y[base + lane] = param[base + lane] + 1.0f;
            if (lane < 16)
                s_y[base + 32 + lane] = param[base + 32 + lane] + 1.0f;
        }
        asm volatile("cp.async.wait_group 0;\n" ::: "memory");
        __syncthreads();                          // carry + smem tile visible to all

        // ---- compute: registers, smem tile, then fully-unrolled stream ----
        float4 acc = make_float4(0.f, 0.f, 0.f, 0.f);
        #pragma unroll
        for (int u = 0; u < PRE; ++u) {
            const float yv = s_y[w + NWARP * u];
            FMA4(yv, m[u]);
        }
        #pragma unroll
        for (int j = SMJ0; j < SMJ1; ++j) {
            const int row = w + NWARP * j;
            const float4 mm = s_mat[(row - SMJ0 * NWARP) * 32 + lane];
            const float  yv = s_y[row];
            FMA4(yv, mm);
        }
        #pragma unroll
        for (int j = SMJ1; j < RPW; ++j) {        // ptxas front-batches these LDG.128s
            const float4 mm = __ldcs(&pm[(size_t)(w + NWARP * j) * RPF4 + lane]);
            const float  yv = s_y[w + NWARP * j];
            FMA4(yv, mm);
        }

        // ---- publish partials; hoist t+1 register prefetch (private, race-free) ----
        ((float4*)s_red[w])[lane] = acc;
        if (t < NT - 1) {
            pm += (size_t)SZ * RPF4;
            #pragma unroll
            for (int u = 0; u < PRE; ++u)
                m[u] = __ldcs(&pm[(size_t)(w + NWARP * u) * RPF4 + lane]);
        }
        __syncthreads();                          // all s_mat reads done; s_red ready

        // ---- t+1 cp.async tile: fills the reduction window with traffic ----
        if (t < NT - 1) {
            #pragma unroll
            for (int k = 0; k < CPT; ++k) {
                int c   = tid + NTHR * k;
                int row = (SMJ0 * NWARP) + (c >> 5);
                int ln  = c & 31;
                cp_async16(s_mat_base + (uint32_t)c * 16,
                           &pm[(size_t)row * RPF4 + ln]);
            }
            asm volatile("cp.async.commit_group;\n" ::: "memory");
        }

        // ---- reduce 16 partials per column, write carry / output ----
        if (tid < SLAB) {
            float sum = 0.f;
            #pragma unroll
            for (int ww = 0; ww < NWARP; ++ww) sum += s_red[ww][tid];
            const int k = kbase + tid;
            if (t == NT - 1) {
                out[b * SZ + k] = sum;                    // pre-ReLU final step
            } else {
                __stcg(&g_carry[t][b][k], fmaxf(sum, 0.f));
            }
            __threadfence();                              // release (writers only)
        }
        __syncthreads();                                  // writers fenced before flag
        if (t < NT - 1 && tid == 0) {
            atomicExch(&g_flag[t][b][s], 1);
        }
    }
}

extern "C" void kernel_launch(void* const* d_in, const int* in_sizes, int n_in,
                              void* d_out, int out_size)
{
    const float* inp   = (const float*)d_in[0];   // [32,24,768,768] f32
    const float* param = (const float*)d_in[1];   // [768] f32
    float* out         = (float*)d_out;           // [32,768] f32

    init_flags_kernel2<<<9, 512>>>();
    dim3 grid(NS, NB);
    scan_kernel<<<grid, NTHR>>>(inp, param, out);
}